// round 17
// baseline (speedup 1.0000x reference)
#include <cuda_runtime.h>
#include <cuda_bf16.h>
#include <cstdint>

// OptionAttentionSum: out[b,o] = (sum_w sum_l [doc[b,l]==opt[b,o,w]] * prob[b,l]) / #nonzero words
//
// R10: epilogue-free design. Matches are rare (~4 per 4096-word row), so the
// division is folded into the table payload and results are emitted at match
// time with fire-and-forget global atomics (REDG, no return):
//   - each (o,w) entry claims its OWN slot (dups get separate slots) with
//     payload {option_id, 1/cnt_o}
//   - probe walks the (tiny) cluster to EMPTY, firing atomicAdd(out[b,o], p*inv)
//     per matching entry
//   - CTA b exclusively owns out row b -> zeroed at entry, no cross-CTA traffic
// Two barriers + the entire lookup/reduce/store tail of R9 are deleted; the CTA
// ends right after the probe loop. (R4's failure was BLOCKING atomics + fences;
// these are rare non-blocking reductions.)

static constexpr int B = 128;
static constexpr int L = 4096;
static constexpr int O = 10;
static constexpr int W = 5;
static constexpr int OW = O * W;          // 50
static constexpr int THREADS = 1024;      // L/4 -> one int4 per thread
static constexpr int TSIZE = 2048;        // hash slots (power of 2), load ~0.024
static constexpr int KEMPTY = (int)0x80000000;  // impossible key (values in [0, 50000))

__device__ __forceinline__ unsigned hash_key(int key) {
    return ((unsigned)key * 2654435761u) >> (32 - 11);   // top 11 bits -> [0,2048)
}

__global__ __launch_bounds__(THREADS, 1)
void oas_kernel(const int* __restrict__ doc_idx,
                const float* __restrict__ doc_prob,
                const int* __restrict__ options,
                float* __restrict__ out) {
    __shared__ int   s_key[TSIZE];
    __shared__ float s_inv[TSIZE];   // payload: 1/(nonzero word count of this entry's option)
    __shared__ int   s_oid[TSIZE];   // payload: option id
    __shared__ int   s_opt[OW];      // cached option keys

    const int b   = blockIdx.x;
    const int tid = threadIdx.x;

    // ---- issue ALL global loads first: doc (2x LDG.128) + options (tid<50) ----
    const int4   d4 = reinterpret_cast<const int4*>(doc_idx  + b * L)[tid];
    const float4 p4 = reinterpret_cast<const float4*>(doc_prob + b * L)[tid];

    int my_key = 0;
    if (tid < OW) my_key = options[b * OW + tid];   // latency overlaps init below

    // ---- zero this CTA's exclusive output row (poisoned 0xAA by harness) ----
    if (tid < O) out[b * O + tid] = 0.0f;

    // ---- init keys: one STS.64 per thread ----
    reinterpret_cast<int2*>(s_key)[tid] = make_int2(KEMPTY, KEMPTY);
    if (tid < OW) s_opt[tid] = my_key;              // only these 50 threads wait on the LDG
    __syncthreads();

    // ---- insert: each (o,w) claims its OWN slot with {oid, 1/cnt} payload ----
    if (tid < OW) {
        const int o = tid / W;
        float cnt = 0.0f;
        #pragma unroll
        for (int w = 0; w < W; w++)
            if (s_opt[o * W + w] != 0) cnt += 1.0f;
        const float inv = 1.0f / cnt;

        unsigned h = hash_key(my_key);
        while (atomicCAS(&s_key[h], KEMPTY, my_key) != KEMPTY)   // claim an EMPTY slot
            h = (h + 1) & (TSIZE - 1);                            // (dups take the next one)
        s_inv[h] = inv;
        s_oid[h] = o;
    }
    __syncthreads();

    // ---- probe: 4 independent first-probe LDS; walk cluster to EMPTY on occupied ----
    const int   dk[4] = {d4.x, d4.y, d4.z, d4.w};
    const float pp[4] = {p4.x, p4.y, p4.z, p4.w};

    unsigned hh[4];
    int      k0[4];
    #pragma unroll
    for (int j = 0; j < 4; j++) hh[j] = hash_key(dk[j]);
    #pragma unroll
    for (int j = 0; j < 4; j++) k0[j] = s_key[hh[j]];

    float* const out_row = out + b * O;
    #pragma unroll
    for (int j = 0; j < 4; j++) {
        unsigned h = hh[j];
        int      k = k0[j];
        while (k != KEMPTY) {                  // first slot EMPTY ~96% -> skip entirely
            if (k == dk[j]) {
                // rare (~4 per row): fire-and-forget reduction, no return wait
                atomicAdd(&out_row[s_oid[h]], pp[j] * s_inv[h]);
            }
            h = (h + 1) & (TSIZE - 1);
            k = s_key[h];
        }
    }
    // no tail: kernel exit flushes the reductions
}

extern "C" void kernel_launch(void* const* d_in, const int* in_sizes, int n_in,
                              void* d_out, int out_size) {
    const int*   doc_idx  = (const int*)d_in[0];     // (B, L) int32 (JAX-downgraded int64)
    const float* doc_prob = (const float*)d_in[1];   // (B, L) float32
    const int*   options  = (const int*)d_in[2];     // (B, O, W) int32
    float*       out      = (float*)d_out;           // (B, O) float32

    oas_kernel<<<B, THREADS>>>(doc_idx, doc_prob, options, out);
}